// round 16
// baseline (speedup 1.0000x reference)
#include <cuda_runtime.h>
#include <cuda_fp16.h>
#include <cstdint>

#define HW 128
#define KSZ 255
#define NTHR 256

// smem byte offsets
#define OFF_WHP 0        // 254 fp16-pairs of wh
#define OFF_WWP 1024     // 254 fp16-pairs of ww
#define OFF_X   4096     // X^T fp16 plane, 128 rows (32KB)
#define SMEM_TOTAL 36864

// K-major fp16 plane: rows x 256B; 16B chunks XOR-swizzled by row&7.
__device__ __forceinline__ uint32_t off_rk(int r, int k) {
    return (uint32_t)(r * 256 + ((((k >> 3) ^ (r & 7)) << 4) | ((k & 7) << 1)));
}

__device__ __forceinline__ uint32_t s2u(const void* p) {
    uint32_t a;
    asm("{ .reg .u64 t; cvta.to.shared.u64 t, %1; cvt.u32.u64 %0, t; }" : "=r"(a) : "l"(p));
    return a;
}

__device__ __forceinline__ void ldsm4(uint32_t* r, uint32_t a) {
    asm volatile("ldmatrix.sync.aligned.m8n8.x4.shared.b16 {%0,%1,%2,%3},[%4];"
                 : "=r"(r[0]), "=r"(r[1]), "=r"(r[2]), "=r"(r[3]) : "r"(a));
}

__device__ __forceinline__ void mma_f16(float* d, uint32_t a0, uint32_t a1, uint32_t a2,
                                        uint32_t a3, uint32_t b0, uint32_t b1) {
    asm volatile(
        "mma.sync.aligned.m16n8k16.row.col.f32.f16.f16.f32 "
        "{%0,%1,%2,%3},{%4,%5,%6,%7},{%8,%9},{%0,%1,%2,%3};"
        : "+f"(d[0]), "+f"(d[1]), "+f"(d[2]), "+f"(d[3])
        : "r"(a0), "r"(a1), "r"(a2), "r"(a3), "r"(b0), "r"(b1));
}

__device__ __forceinline__ uint32_t pack2(float a, float b) {
    __half2 h = __floats2half2_rn(a, b);
    return *(uint32_t*)&h;
}

__device__ __forceinline__ uint32_t lds32(uint32_t addr) {
    uint32_t v;
    asm volatile("ld.shared.b32 %0, [%1];" : "=r"(v) : "r"(addr));
    return v;
}

__device__ __forceinline__ float ldg_cs(const float* p) {
    float v;
    asm volatile("ld.global.cs.f32 %0, [%1];" : "=f"(v) : "l"(p));
    return v;
}

__device__ __forceinline__ void stg_cs64(float* p, float a, float b) {
    asm volatile("st.global.cs.v2.f32 [%0], {%1, %2};" :: "l"(p), "f"(a), "f"(b)
                 : "memory");
}

extern "C" __global__ void __launch_bounds__(NTHR, 2)
conv_mma_kernel(const float* __restrict__ x,
                const float* __restrict__ wh, const float* __restrict__ bh,
                const float* __restrict__ ww, const float* __restrict__ bw,
                float* __restrict__ out) {
    extern __shared__ __align__(1024) char smem[];
    uint32_t sb = s2u(smem);
    int t = threadIdx.x, lane = t & 31, wid = t >> 5;
    int img = blockIdx.x, c = img & 255;
    size_t base = (size_t)img << 14;

    int w = t & 127, ihalf = t >> 7;
    const float* xp = x + base + w;

    // Prologue: LDGs for k-blocks 0 and 1 (chunk i0 = 16*kk + 8*ihalf).
    float f0[8], f1[8];
#pragma unroll
    for (int j = 0; j < 8; j++) f0[j] = ldg_cs(xp + (size_t)(8 * ihalf + j) * HW);
#pragma unroll
    for (int j = 0; j < 8; j++) f1[j] = ldg_cs(xp + (size_t)(16 + 8 * ihalf + j) * HW);

    // Weight pair tables: p[i] = (f16(w[i]), f16(w[i+1])), i in [0,253].
    if (t < KSZ - 1) {
        const float* wp = wh + c * KSZ;
        *(uint32_t*)(smem + OFF_WHP + 4 * t) = pack2(wp[t], wp[t + 1]);
        wp = ww + c * KSZ;
        *(uint32_t*)(smem + OFF_WWP + 4 * t) = pack2(wp[t], wp[t + 1]);
    }
    float bhc = bh[c], bwc = bw[c];

    int g = lane >> 2, tt2 = (lane & 3) * 2;
    int mbase = wid * 16;
    int nB = lane & 7, khB = (lane & 15) >> 3, tB = lane >> 4;
    uint32_t pwh = sb + OFF_WHP, pww = sb + OFF_WWP;

    // ---- Stage 1, fused with convert: at iter kk, store k-block kk, sync,
    //      prefetch block kk+2, then gemm-step kk. ----
    float d1[16][4];
#pragma unroll
    for (int tn = 0; tn < 16; tn++)
#pragma unroll
        for (int q = 0; q < 4; q++) d1[tn][q] = bhc;

    int ib1 = 127 + tt2 - g - mbase;
    uint32_t W1a = 0, W1b = 0, W1c = 0;
    uint32_t bRow = (uint32_t)(8 * tB + nB) * 256;

#pragma unroll
    for (int kk = 0; kk < 8; kk++) {
        // Store this k-block's chunk (8 i's) into the plane.
        {
            float* fc = (kk & 1) ? f1 : f0;
            uint32_t q[4];
#pragma unroll
            for (int j = 0; j < 4; j++) q[j] = pack2(fc[2 * j], fc[2 * j + 1]);
            *(uint4*)(smem + OFF_X + off_rk(w, 16 * kk + 8 * ihalf)) = *(uint4*)q;
        }
        __syncthreads();   // k-block kk complete (and tables, for kk=0)

        // Weight ring.
        if (kk == 0) {
            W1a = lds32(pwh + 4u * (uint32_t)(ib1 - 8));
            W1b = lds32(pwh + 4u * (uint32_t)(ib1));
            W1c = lds32(pwh + 4u * (uint32_t)(ib1 + 8));
        } else {
            W1a = W1c;
            W1b = lds32(pwh + 4u * (uint32_t)(ib1 + 16 * kk));
            W1c = lds32(pwh + 4u * (uint32_t)(ib1 + 16 * kk + 8));
        }

        // Prefetch block kk+2 into the buffer just freed.
        if (kk < 6) {
            float* fc = (kk & 1) ? f1 : f0;
            int i0 = 16 * (kk + 2) + 8 * ihalf;
#pragma unroll
            for (int j = 0; j < 8; j++) fc[j] = ldg_cs(xp + (size_t)(i0 + j) * HW);
        }

        // Gemm step kk.
        uint32_t bx = (uint32_t)(((2 * kk + khB) ^ nB) << 4);
        uint32_t bb[8][4];
#pragma unroll
        for (int gg = 0; gg < 8; gg++)
            ldsm4(bb[gg], sb + OFF_X + bRow + (uint32_t)gg * 4096 + bx);
#pragma unroll
        for (int tn = 0; tn < 16; tn++)
            mma_f16(d1[tn], W1b, W1a, W1c, W1b,
                    bb[tn >> 1][(tn & 1) * 2], bb[tn >> 1][(tn & 1) * 2 + 1]);
    }

    // In-register handoff: Y (f32 accums) -> stage-2 A-fragments (fp16x2).
    uint32_t fA[8][4];
#pragma unroll
    for (int q = 0; q < 8; q++) {
        fA[q][0] = pack2(d1[2 * q][0], d1[2 * q][1]);
        fA[q][1] = pack2(d1[2 * q][2], d1[2 * q][3]);
        fA[q][2] = pack2(d1[2 * q + 1][0], d1[2 * q + 1][1]);
        fA[q][3] = pack2(d1[2 * q + 1][2], d1[2 * q + 1][3]);
    }

    // ---- Stage 2: Z[h][w'] = Y @ Toep(ww)^T, same rows, all 128 w'. ----
    float d2[16][4];
#pragma unroll
    for (int tn = 0; tn < 16; tn++)
#pragma unroll
        for (int q = 0; q < 4; q++) d2[tn][q] = bwc;

    {
        int ib2 = 7 + tt2 - g;
        uint32_t W2[17];
#pragma unroll
        for (int j = 0; j < 17; j++) W2[j] = lds32(pww + 4u * (uint32_t)(ib2 + 8 * j));
#pragma unroll
        for (int q = 0; q < 8; q++) {
            if (q) {
#pragma unroll
                for (int j = 0; j < 15; j++) W2[j] = W2[j + 2];
                W2[15] = lds32(pww + 4u * (uint32_t)(ib2 + 8 * (2 * q + 15)));
                W2[16] = lds32(pww + 4u * (uint32_t)(ib2 + 8 * (2 * q + 16)));
            }
#pragma unroll
            for (int tn = 0; tn < 16; tn++)
                mma_f16(d2[tn], fA[q][0], fA[q][1], fA[q][2], fA[q][3],
                        W2[15 - tn], W2[16 - tn]);
        }
    }

    // Final epilogue: Z -> global, streaming stores.
    {
        int r0 = mbase + g;
#pragma unroll
        for (int tn = 0; tn < 16; tn++) {
            int c0 = 8 * tn + tt2;
            stg_cs64(out + base + (size_t)r0 * HW + c0, d2[tn][0], d2[tn][1]);
            stg_cs64(out + base + (size_t)(r0 + 8) * HW + c0, d2[tn][2], d2[tn][3]);
        }
    }
}

extern "C" void kernel_launch(void* const* d_in, const int* in_sizes, int n_in,
                              void* d_out, int out_size) {
    const float* x  = (const float*)d_in[0];
    const float* wh = (const float*)d_in[1];
    const float* bh = (const float*)d_in[2];
    const float* ww = (const float*)d_in[3];
    const float* bw = (const float*)d_in[4];
    float* out = (float*)d_out;

    int nimg = in_sizes[0] >> 14;
    cudaFuncSetAttribute(conv_mma_kernel,
                         cudaFuncAttributeMaxDynamicSharedMemorySize, SMEM_TOTAL);
    conv_mma_kernel<<<nimg, NTHR, SMEM_TOTAL>>>(x, wh, bh, ww, bw, out);
}

// round 17
// speedup vs baseline: 1.2734x; 1.2734x over previous
#include <cuda_runtime.h>
#include <cuda_fp16.h>
#include <cstdint>

#define HW 128
#define KSZ 255
#define NTHR 256

// smem byte offsets
#define OFF_WHP 0        // 254 fp16-pairs of wh
#define OFF_WWP 1024     // 254 fp16-pairs of ww
#define OFF_X   4096     // X^T fp16 plane, 128 rows (32KB)
#define SMEM_TOTAL 36864

// K-major fp16 plane: rows x 256B; 16B chunks XOR-swizzled by row&7.
__device__ __forceinline__ uint32_t off_rk(int r, int k) {
    return (uint32_t)(r * 256 + ((((k >> 3) ^ (r & 7)) << 4) | ((k & 7) << 1)));
}

__device__ __forceinline__ uint32_t s2u(const void* p) {
    uint32_t a;
    asm("{ .reg .u64 t; cvta.to.shared.u64 t, %1; cvt.u32.u64 %0, t; }" : "=r"(a) : "l"(p));
    return a;
}

__device__ __forceinline__ void ldsm4(uint32_t* r, uint32_t a) {
    asm volatile("ldmatrix.sync.aligned.m8n8.x4.shared.b16 {%0,%1,%2,%3},[%4];"
                 : "=r"(r[0]), "=r"(r[1]), "=r"(r[2]), "=r"(r[3]) : "r"(a));
}

__device__ __forceinline__ void mma_f16(float* d, uint32_t a0, uint32_t a1, uint32_t a2,
                                        uint32_t a3, uint32_t b0, uint32_t b1) {
    asm volatile(
        "mma.sync.aligned.m16n8k16.row.col.f32.f16.f16.f32 "
        "{%0,%1,%2,%3},{%4,%5,%6,%7},{%8,%9},{%0,%1,%2,%3};"
        : "+f"(d[0]), "+f"(d[1]), "+f"(d[2]), "+f"(d[3])
        : "r"(a0), "r"(a1), "r"(a2), "r"(a3), "r"(b0), "r"(b1));
}

__device__ __forceinline__ uint32_t pack2(float a, float b) {
    __half2 h = __floats2half2_rn(a, b);
    return *(uint32_t*)&h;
}

__device__ __forceinline__ uint32_t lds32(uint32_t addr) {
    uint32_t v;
    asm volatile("ld.shared.b32 %0, [%1];" : "=r"(v) : "r"(addr));
    return v;
}

__device__ __forceinline__ float ldg_cs(const float* p) {
    float v;
    asm volatile("ld.global.cs.f32 %0, [%1];" : "=f"(v) : "l"(p));
    return v;
}

__device__ __forceinline__ void stg_cs64(float* p, float a, float b) {
    asm volatile("st.global.cs.v2.f32 [%0], {%1, %2};" :: "l"(p), "f"(a), "f"(b)
                 : "memory");
}

extern "C" __global__ void __launch_bounds__(NTHR, 2)
conv_mma_kernel(const float* __restrict__ x,
                const float* __restrict__ wh, const float* __restrict__ bh,
                const float* __restrict__ ww, const float* __restrict__ bw,
                float* __restrict__ out) {
    extern __shared__ __align__(1024) char smem[];
    uint32_t sb = s2u(smem);
    int t = threadIdx.x, lane = t & 31, wid = t >> 5;
    int img = blockIdx.x, c = img & 255;
    size_t base = (size_t)img << 14;

    // Weight pair tables: p[i] = (f16(w[i]), f16(w[i+1])), i in [0,253].
    if (t < KSZ - 1) {
        const float* wp = wh + c * KSZ;
        *(uint32_t*)(smem + OFF_WHP + 4 * t) = pack2(wp[t], wp[t + 1]);
        wp = ww + c * KSZ;
        *(uint32_t*)(smem + OFF_WWP + 4 * t) = pack2(wp[t], wp[t + 1]);
    }
    float bhc = bh[c], bwc = bw[c];

    // X^T fp16 plane: plane[w][i] = f16(X[i][w]).
    // Wide LDG batches (32 outstanding) before any pack/STS -> high MLP.
    {
        int w = t & 127, ihalf = t >> 7;
        const float* xp = x + base + w;
#pragma unroll
        for (int half = 0; half < 2; half++) {
            int ibase = ihalf * 64 + half * 32;
            float f[32];
#pragma unroll
            for (int j = 0; j < 32; j++)
                f[j] = ldg_cs(xp + (size_t)(ibase + j) * HW);
#pragma unroll
            for (int blk = 0; blk < 4; blk++) {
                uint32_t q[4];
#pragma unroll
                for (int j = 0; j < 4; j++)
                    q[j] = pack2(f[8 * blk + 2 * j], f[8 * blk + 2 * j + 1]);
                *(uint4*)(smem + OFF_X + off_rk(w, ibase + 8 * blk)) = *(uint4*)q;
            }
        }
    }
    __syncthreads();   // the ONLY barrier

    int g = lane >> 2, tt2 = (lane & 3) * 2;
    int mbase = wid * 16;             // warp owns output rows mbase..mbase+15
    int nB = lane & 7, khB = (lane & 15) >> 3, tB = lane >> 4;
    uint32_t pwh = sb + OFF_WHP, pww = sb + OFF_WWP;

    // ---- Stage 1: Y[h][w] = Toep(wh) @ X, rows mbase..mbase+15, all 128 w. ----
    float d1[16][4];
#pragma unroll
    for (int tn = 0; tn < 16; tn++)
#pragma unroll
        for (int q = 0; q < 4; q++) d1[tn][q] = bhc;

    {
        int ib1 = 127 + tt2 - g - mbase;           // in [8, 133]
        uint32_t W1a = lds32(pwh + 4u * (uint32_t)(ib1 - 8));
        uint32_t W1b = lds32(pwh + 4u * (uint32_t)(ib1));
        uint32_t W1c = lds32(pwh + 4u * (uint32_t)(ib1 + 8));
        uint32_t bRow = (uint32_t)(8 * tB + nB) * 256;
#pragma unroll
        for (int kk = 0; kk < 8; kk++) {
            if (kk) {
                W1a = W1c;
                W1b = lds32(pwh + 4u * (uint32_t)(ib1 + 16 * kk));
                W1c = lds32(pwh + 4u * (uint32_t)(ib1 + 16 * kk + 8));
            }
            uint32_t bx = (uint32_t)(((2 * kk + khB) ^ nB) << 4);
            uint32_t bb[8][4];
#pragma unroll
            for (int gg = 0; gg < 8; gg++)
                ldsm4(bb[gg], sb + OFF_X + bRow + (uint32_t)gg * 4096 + bx);
#pragma unroll
            for (int tn = 0; tn < 16; tn++)
                mma_f16(d1[tn], W1b, W1a, W1c, W1b,
                        bb[tn >> 1][(tn & 1) * 2], bb[tn >> 1][(tn & 1) * 2 + 1]);
        }
    }

    // In-register handoff: Y (f32 accums) -> stage-2 A-fragments (fp16x2).
    uint32_t fA[8][4];
#pragma unroll
    for (int q = 0; q < 8; q++) {
        fA[q][0] = pack2(d1[2 * q][0], d1[2 * q][1]);
        fA[q][1] = pack2(d1[2 * q][2], d1[2 * q][3]);
        fA[q][2] = pack2(d1[2 * q + 1][0], d1[2 * q + 1][1]);
        fA[q][3] = pack2(d1[2 * q + 1][2], d1[2 * q + 1][3]);
    }

    // ---- Stage 2: Z[h][w'] = Y @ Toep(ww)^T, same rows, all 128 w'. ----
    float d2[16][4];
#pragma unroll
    for (int tn = 0; tn < 16; tn++)
#pragma unroll
        for (int q = 0; q < 4; q++) d2[tn][q] = bwc;

    {
        int ib2 = 7 + tt2 - g;                    // in [0, 13]
        uint32_t W2[17];                          // W2[j] = tab[ib2 + 8*(2q + j)]
#pragma unroll
        for (int j = 0; j < 17; j++) W2[j] = lds32(pww + 4u * (uint32_t)(ib2 + 8 * j));
#pragma unroll
        for (int q = 0; q < 8; q++) {
            if (q) {
#pragma unroll
                for (int j = 0; j < 15; j++) W2[j] = W2[j + 2];
                W2[15] = lds32(pww + 4u * (uint32_t)(ib2 + 8 * (2 * q + 15)));
                W2[16] = lds32(pww + 4u * (uint32_t)(ib2 + 8 * (2 * q + 16)));
            }
#pragma unroll
            for (int tn = 0; tn < 16; tn++)
                mma_f16(d2[tn], fA[q][0], fA[q][1], fA[q][2], fA[q][3],
                        W2[15 - tn], W2[16 - tn]);
        }
    }

    // Final epilogue: Z -> global, streaming stores (never re-read).
    {
        int r0 = mbase + g;
#pragma unroll
        for (int tn = 0; tn < 16; tn++) {
            int c0 = 8 * tn + tt2;
            stg_cs64(out + base + (size_t)r0 * HW + c0, d2[tn][0], d2[tn][1]);
            stg_cs64(out + base + (size_t)(r0 + 8) * HW + c0, d2[tn][2], d2[tn][3]);
        }
    }
}

extern "C" void kernel_launch(void* const* d_in, const int* in_sizes, int n_in,
                              void* d_out, int out_size) {
    const float* x  = (const float*)d_in[0];
    const float* wh = (const float*)d_in[1];
    const float* bh = (const float*)d_in[2];
    const float* ww = (const float*)d_in[3];
    const float* bw = (const float*)d_in[4];
    float* out = (float*)d_out;

    int nimg = in_sizes[0] >> 14;
    cudaFuncSetAttribute(conv_mma_kernel,
                         cudaFuncAttributeMaxDynamicSharedMemorySize, SMEM_TOTAL);
    conv_mma_kernel<<<nimg, NTHR, SMEM_TOTAL>>>(x, wh, bh, ww, bw, out);
}